// round 1
// baseline (speedup 1.0000x reference)
#include <cuda_runtime.h>
#include <math.h>

#define BATCH 2048
#define NEXP 8
#define NCLS 100
#define HID 1024
#define GATEH 2048
#define FEAT 2048

// ---------------- scratch (device globals; no allocation allowed) -------------
__device__ float g_convout[134217728];            // max conv output: [2048,64,32,32]
__device__ float g_poolA[33554432];               // max pooled: [2048,64,16,16]
__device__ float g_poolB[16777216];               // [2048,128,8,8] / final f [2048,512,2,2]
__device__ float g_hid[BATCH * GATEH];            // gating hidden (reused)
__device__ float g_clean[BATCH * NEXP];
__device__ float g_rawstd[BATCH * NEXP];
__device__ float g_gates[BATCH * NEXP];
__device__ float g_prob[BATCH * NEXP];
__device__ float g_eh[(size_t)NEXP * BATCH * HID];        // [8,2048,1024]
__device__ float g_eh2[(size_t)NEXP * BATCH * (HID / 2)]; // [8,2048,512]
__device__ float g_eo[(size_t)NEXP * BATCH * NCLS];       // [8,2048,100]
__device__ float g_imp[NEXP];
__device__ float g_load[NEXP];

#define BM 64
#define BN 64
#define BK 16

// ---------------- implicit-im2col conv GEMM + bias + BN + ReLU ----------------
// C[m=co][n=b*HW+pos] = sum_k W[co,k] * patch[k,n], k = ci*9 + ky*3 + kx
__global__ __launch_bounds__(256) void conv_gemm_kernel(
    const float* __restrict__ in, const float* __restrict__ w,
    const float* __restrict__ cb, const float* __restrict__ gam,
    const float* __restrict__ bet, float* __restrict__ out,
    int Cin, int Cout, int H, int logW, int logHW) {
  const int HW = 1 << logHW;
  const int W = 1 << logW;
  const int Ktot = Cin * 9;
  const int n0 = blockIdx.x * BN;
  const int m0 = blockIdx.y * BM;

  __shared__ float As[BK][BM + 1];
  __shared__ float Bs[BK][BN + 1];

  float acc[4][4];
#pragma unroll
  for (int i = 0; i < 4; i++)
#pragma unroll
    for (int j = 0; j < 4; j++) acc[i][j] = 0.f;

  const int tid = threadIdx.x;
  const int tx = tid & 15, ty = tid >> 4;

  for (int k0 = 0; k0 < Ktot; k0 += BK) {
#pragma unroll
    for (int i = 0; i < 4; i++) {
      int l = tid + i * 256;
      int k = l & 15, m = l >> 4;
      int gk = k0 + k, gm = m0 + m;
      As[k][m] = (gk < Ktot && gm < Cout) ? w[gm * Ktot + gk] : 0.f;
    }
#pragma unroll
    for (int i = 0; i < 4; i++) {
      int l = tid + i * 256;
      int n = l & 63, k = l >> 6;
      int gk = k0 + k, gn = n0 + n;
      float v = 0.f;
      if (gk < Ktot) {
        int ci = gk / 9;
        int r = gk - ci * 9;
        int ky = r / 3;
        int kx = r - ky * 3;
        int b = gn >> logHW;
        int pos = gn & (HW - 1);
        int y = pos >> logW, x = pos & (W - 1);
        int iy = y + ky - 1, ix = x + kx - 1;
        if ((unsigned)iy < (unsigned)H && (unsigned)ix < (unsigned)H)
          v = in[((b * Cin + ci) * H + iy) * H + ix];
      }
      Bs[k][n] = v;
    }
    __syncthreads();
#pragma unroll
    for (int kk = 0; kk < BK; kk++) {
      float a[4], bv[4];
#pragma unroll
      for (int i = 0; i < 4; i++) a[i] = As[kk][ty * 4 + i];
#pragma unroll
      for (int j = 0; j < 4; j++) bv[j] = Bs[kk][tx * 4 + j];
#pragma unroll
      for (int i = 0; i < 4; i++)
#pragma unroll
        for (int j = 0; j < 4; j++) acc[i][j] = fmaf(a[i], bv[j], acc[i][j]);
    }
    __syncthreads();
  }

#pragma unroll
  for (int i = 0; i < 4; i++) {
    int m = m0 + ty * 4 + i;
    if (m >= Cout) continue;
    float sc = gam[m] * rsqrtf(1.00001f);
    float cbm = cb[m], bem = bet[m];
#pragma unroll
    for (int j = 0; j < 4; j++) {
      int n = n0 + tx * 4 + j;
      int b = n >> logHW;
      int pos = n & (HW - 1);
      float v = (acc[i][j] + cbm) * sc + bem;
      v = fmaxf(v, 0.f);
      out[((size_t)(b * Cout + m) << logHW) + pos] = v;
    }
  }
}

// ---------------- 2x2 max pool (stride 2) ----------------
__global__ void pool_kernel(const float* __restrict__ in, float* __restrict__ out,
                            int C, int H) {
  int Hp = H >> 1;
  int total = BATCH * C * Hp * Hp;
  int idx = blockIdx.x * blockDim.x + threadIdx.x;
  if (idx >= total) return;
  int px = idx % Hp;
  int t = idx / Hp;
  int py = t % Hp; t /= Hp;
  int c = t % C;
  int b = t / C;
  const float* p = in + ((size_t)(b * C + c) * H + py * 2) * H + px * 2;
  out[idx] = fmaxf(fmaxf(p[0], p[1]), fmaxf(p[H], p[H + 1]));
}

// ---------------- generic batched SGEMM: C = act(A@B + bias[n]) ----------------
__global__ __launch_bounds__(256) void sgemm_kernel(
    const float* __restrict__ A, const float* __restrict__ Bmat,
    const float* __restrict__ bias, float* __restrict__ C,
    int M, int N, int K, int relu,
    long long sA, long long sB, long long sBias, long long sC) {
  const float* Ab = A + (long long)blockIdx.z * sA;
  const float* Bb = Bmat + (long long)blockIdx.z * sB;
  const float* biasb = bias + (long long)blockIdx.z * sBias;
  float* Cb = C + (long long)blockIdx.z * sC;

  const int n0 = blockIdx.x * BN;
  const int m0 = blockIdx.y * BM;

  __shared__ float As[BK][BM + 1];
  __shared__ float Bs[BK][BN + 1];

  float acc[4][4];
#pragma unroll
  for (int i = 0; i < 4; i++)
#pragma unroll
    for (int j = 0; j < 4; j++) acc[i][j] = 0.f;

  const int tid = threadIdx.x;
  const int tx = tid & 15, ty = tid >> 4;

  for (int k0 = 0; k0 < K; k0 += BK) {
#pragma unroll
    for (int i = 0; i < 4; i++) {
      int l = tid + i * 256;
      int k = l & 15, m = l >> 4;
      int gk = k0 + k, gm = m0 + m;
      As[k][m] = (gm < M && gk < K) ? Ab[(size_t)gm * K + gk] : 0.f;
    }
#pragma unroll
    for (int i = 0; i < 4; i++) {
      int l = tid + i * 256;
      int n = l & 63, k = l >> 6;
      int gk = k0 + k, gn = n0 + n;
      Bs[k][n] = (gk < K && gn < N) ? Bb[(size_t)gk * N + gn] : 0.f;
    }
    __syncthreads();
#pragma unroll
    for (int kk = 0; kk < BK; kk++) {
      float a[4], bv[4];
#pragma unroll
      for (int i = 0; i < 4; i++) a[i] = As[kk][ty * 4 + i];
#pragma unroll
      for (int j = 0; j < 4; j++) bv[j] = Bs[kk][tx * 4 + j];
#pragma unroll
      for (int i = 0; i < 4; i++)
#pragma unroll
        for (int j = 0; j < 4; j++) acc[i][j] = fmaf(a[i], bv[j], acc[i][j]);
    }
    __syncthreads();
  }

#pragma unroll
  for (int i = 0; i < 4; i++) {
    int m = m0 + ty * 4 + i;
    if (m >= M) continue;
#pragma unroll
    for (int j = 0; j < 4; j++) {
      int n = n0 + tx * 4 + j;
      if (n >= N) continue;
      float v = acc[i][j] + biasb[n];
      if (relu) v = fmaxf(v, 0.f);
      Cb[(size_t)m * N + n] = v;
    }
  }
}

// ---------------- noisy top-k gating (per row) ----------------
__global__ void gating_kernel(const float* __restrict__ clean,
                              const float* __restrict__ rawstd,
                              const float* __restrict__ noise,
                              float* __restrict__ gates, float* __restrict__ prob) {
  int b = blockIdx.x * blockDim.x + threadIdx.x;
  if (b >= BATCH) return;
  float c[NEXP], sd[NEXP], nz[NEXP];
#pragma unroll
  for (int e = 0; e < NEXP; e++) {
    c[e] = clean[b * NEXP + e];
    float rs = rawstd[b * NEXP + e];
    float sp = (rs > 20.f) ? rs : log1pf(expf(rs));
    sd[e] = sp + 0.01f;
    nz[e] = c[e] + noise[b * NEXP + e] * sd[e];
  }
  // top-3 of the noisy logits (value-based; strict > keeps earliest index like lax.top_k)
  int i0 = 0; float v0 = nz[0];
#pragma unroll
  for (int e = 1; e < NEXP; e++) if (nz[e] > v0) { v0 = nz[e]; i0 = e; }
  int i1 = -1; float v1 = -1e30f;
#pragma unroll
  for (int e = 0; e < NEXP; e++) if (e != i0 && nz[e] > v1) { v1 = nz[e]; i1 = e; }
  float v2 = -1e30f;
#pragma unroll
  for (int e = 0; e < NEXP; e++) if (e != i0 && e != i1 && nz[e] > v2) v2 = nz[e];

  float e1 = expf(v1 - v0);
  float inv = 1.f / (1.f + e1);
  const float kInvSqrt2 = 0.70710678118654752440f;
#pragma unroll
  for (int e = 0; e < NEXP; e++) {
    float g = (e == i0) ? inv : ((e == i1) ? e1 * inv : 0.f);
    gates[b * NEXP + e] = g;
    // th_in = 3rd-largest (v2), th_out = 2nd-largest (v1)
    float th = (nz[e] > v2) ? v2 : v1;
    float z = (c[e] - th) / sd[e];
    prob[b * NEXP + e] = 0.5f * (1.f + erff(z * kInvSqrt2));
  }
}

// ---------------- deterministic per-expert reductions ----------------
__global__ void moe_reduce_kernel(const float* __restrict__ gates,
                                  const float* __restrict__ prob,
                                  float* __restrict__ imp, float* __restrict__ loadv) {
  int e = blockIdx.x;
  int t = threadIdx.x;
  __shared__ float s1[256], s2[256];
  float a = 0.f, b = 0.f;
  for (int i = t; i < BATCH; i += 256) {
    a += gates[i * NEXP + e];
    b += prob[i * NEXP + e];
  }
  s1[t] = a; s2[t] = b;
  __syncthreads();
  for (int s = 128; s > 0; s >>= 1) {
    if (t < s) { s1[t] += s1[t + s]; s2[t] += s2[t + s]; }
    __syncthreads();
  }
  if (t == 0) { imp[e] = s1[0]; loadv[e] = s2[0]; }
}

__global__ void loss_kernel(const float* __restrict__ imp,
                            const float* __restrict__ loadv,
                            float* __restrict__ out) {
  float m1 = 0.f, m2 = 0.f;
  for (int e = 0; e < NEXP; e++) { m1 += imp[e]; m2 += loadv[e]; }
  m1 *= 0.125f; m2 *= 0.125f;
  float v1 = 0.f, v2 = 0.f;
  for (int e = 0; e < NEXP; e++) {
    float d1 = imp[e] - m1; v1 += d1 * d1;
    float d2 = loadv[e] - m2; v2 += d2 * d2;
  }
  v1 /= 7.f; v2 /= 7.f;  // ddof=1
  out[0] = v1 / (m1 * m1 + 1e-10f) + v2 / (m2 * m2 + 1e-10f);
}

// ---------------- gate-weighted combine: y[b,c] = sum_e g[b,e]*eo[e,b,c] ------
__global__ void combine_kernel(const float* __restrict__ gates,
                               const float* __restrict__ eo, float* __restrict__ y) {
  int idx = blockIdx.x * blockDim.x + threadIdx.x;
  if (idx >= BATCH * NCLS) return;
  int b = idx / NCLS;
  int c = idx - b * NCLS;
  float s = 0.f;
#pragma unroll
  for (int e = 0; e < NEXP; e++)
    s += gates[b * NEXP + e] * eo[((size_t)e * BATCH + b) * NCLS + c];
  y[idx] = s;
}

// ================================ launch ======================================
extern "C" void kernel_launch(void* const* d_in, const int* in_sizes, int n_in,
                              void* d_out, int out_size) {
  const float* x    = (const float*)d_in[0];
  const float* noise= (const float*)d_in[1];
  const float* cw1 = (const float*)d_in[2],  *cb1 = (const float*)d_in[3];
  const float* g1  = (const float*)d_in[4],  *be1 = (const float*)d_in[5];
  const float* cw2 = (const float*)d_in[6],  *cb2 = (const float*)d_in[7];
  const float* g2  = (const float*)d_in[8],  *be2 = (const float*)d_in[9];
  const float* cw3 = (const float*)d_in[10], *cb3 = (const float*)d_in[11];
  const float* g3  = (const float*)d_in[12], *be3 = (const float*)d_in[13];
  const float* cw4 = (const float*)d_in[14], *cb4 = (const float*)d_in[15];
  const float* g4  = (const float*)d_in[16], *be4 = (const float*)d_in[17];
  const float* wg1 = (const float*)d_in[18], *wg1b= (const float*)d_in[19];
  const float* wg2 = (const float*)d_in[20], *wg2b= (const float*)d_in[21];
  const float* wn1 = (const float*)d_in[22], *wn1b= (const float*)d_in[23];
  const float* wn2 = (const float*)d_in[24], *wn2b= (const float*)d_in[25];
  const float* eW1 = (const float*)d_in[26], *eb1 = (const float*)d_in[27];
  const float* eW2 = (const float*)d_in[28], *eb2 = (const float*)d_in[29];
  const float* eW3 = (const float*)d_in[30], *eb3 = (const float*)d_in[31];

  float *convout, *poolA, *poolB, *hid, *clean, *rawstd, *gates, *prob;
  float *eh, *eh2, *eo, *imp, *loadv;
  cudaGetSymbolAddress((void**)&convout, g_convout);
  cudaGetSymbolAddress((void**)&poolA, g_poolA);
  cudaGetSymbolAddress((void**)&poolB, g_poolB);
  cudaGetSymbolAddress((void**)&hid, g_hid);
  cudaGetSymbolAddress((void**)&clean, g_clean);
  cudaGetSymbolAddress((void**)&rawstd, g_rawstd);
  cudaGetSymbolAddress((void**)&gates, g_gates);
  cudaGetSymbolAddress((void**)&prob, g_prob);
  cudaGetSymbolAddress((void**)&eh, g_eh);
  cudaGetSymbolAddress((void**)&eh2, g_eh2);
  cudaGetSymbolAddress((void**)&eo, g_eo);
  cudaGetSymbolAddress((void**)&imp, g_imp);
  cudaGetSymbolAddress((void**)&loadv, g_load);

  float* out = (float*)d_out;

  // ---- conv stack (conv+bias+BN+ReLU fused, then 2x2 maxpool) ----
  // conv1: 3 -> 64, H=32
  {
    int N = BATCH * 1024;
    conv_gemm_kernel<<<dim3(N / BN, 1), 256>>>(x, cw1, cb1, g1, be1, convout, 3, 64, 32, 5, 10);
    int tot = BATCH * 64 * 16 * 16;
    pool_kernel<<<(tot + 255) / 256, 256>>>(convout, poolA, 64, 32);
  }
  // conv2: 64 -> 128, H=16
  {
    int N = BATCH * 256;
    conv_gemm_kernel<<<dim3(N / BN, 2), 256>>>(poolA, cw2, cb2, g2, be2, convout, 64, 128, 16, 4, 8);
    int tot = BATCH * 128 * 8 * 8;
    pool_kernel<<<(tot + 255) / 256, 256>>>(convout, poolB, 128, 16);
  }
  // conv3: 128 -> 256, H=8
  {
    int N = BATCH * 64;
    conv_gemm_kernel<<<dim3(N / BN, 4), 256>>>(poolB, cw3, cb3, g3, be3, convout, 128, 256, 8, 3, 6);
    int tot = BATCH * 256 * 4 * 4;
    pool_kernel<<<(tot + 255) / 256, 256>>>(convout, poolA, 256, 8);
  }
  // conv4: 256 -> 512, H=4
  {
    int N = BATCH * 16;
    conv_gemm_kernel<<<dim3(N / BN, 8), 256>>>(poolA, cw4, cb4, g4, be4, convout, 256, 512, 4, 2, 4);
    int tot = BATCH * 512 * 2 * 2;
    pool_kernel<<<(tot + 255) / 256, 256>>>(convout, poolB, 512, 4);
  }
  const float* f = poolB;  // [2048, 2048] flattened NCHW

  // ---- gating nets ----
  sgemm_kernel<<<dim3(GATEH / BN, BATCH / BM, 1), 256>>>(
      f, wg1, wg1b, hid, BATCH, GATEH, FEAT, 1, 0, 0, 0, 0);
  sgemm_kernel<<<dim3(1, BATCH / BM, 1), 256>>>(
      hid, wg2, wg2b, clean, BATCH, NEXP, GATEH, 0, 0, 0, 0, 0);
  sgemm_kernel<<<dim3(GATEH / BN, BATCH / BM, 1), 256>>>(
      f, wn1, wn1b, hid, BATCH, GATEH, FEAT, 1, 0, 0, 0, 0);
  sgemm_kernel<<<dim3(1, BATCH / BM, 1), 256>>>(
      hid, wn2, wn2b, rawstd, BATCH, NEXP, GATEH, 0, 0, 0, 0, 0);

  gating_kernel<<<BATCH / 256, 256>>>(clean, rawstd, noise, gates, prob);
  moe_reduce_kernel<<<NEXP, 256>>>(gates, prob, imp, loadv);

  // ---- dense experts (batched over blockIdx.z = expert) ----
  sgemm_kernel<<<dim3(HID / BN, BATCH / BM, NEXP), 256>>>(
      f, eW1, eb1, eh, BATCH, HID, FEAT, 1,
      0, (long long)FEAT * HID, HID, (long long)BATCH * HID);
  sgemm_kernel<<<dim3((HID / 2) / BN, BATCH / BM, NEXP), 256>>>(
      eh, eW2, eb2, eh2, BATCH, HID / 2, HID, 1,
      (long long)BATCH * HID, (long long)HID * (HID / 2), HID / 2,
      (long long)BATCH * (HID / 2));
  sgemm_kernel<<<dim3((NCLS + BN - 1) / BN, BATCH / BM, NEXP), 256>>>(
      eh2, eW3, eb3, eo, BATCH, NCLS, HID / 2, 0,
      (long long)BATCH * (HID / 2), (long long)(HID / 2) * NCLS, NCLS,
      (long long)BATCH * NCLS);

  // ---- outputs: y [B,C] then loss scalar ----
  combine_kernel<<<(BATCH * NCLS + 255) / 256, 256>>>(gates, eo, out);
  if (out_size >= BATCH * NCLS + 1)
    loss_kernel<<<1, 1>>>(imp, loadv, out + BATCH * NCLS);
}

// round 2
// speedup vs baseline: 1.4790x; 1.4790x over previous
#include <cuda_runtime.h>
#include <math.h>

#define BATCH 2048
#define NEXP 8
#define NCLS 100
#define HID 1024
#define GATEH 2048
#define FEAT 2048

typedef unsigned long long u64;

// ---------------- scratch (device globals; no allocation allowed) -------------
__device__ float g_convout[134217728];            // max conv output: [2048,64,32,32]
__device__ float g_poolA[33554432];
__device__ float g_poolB[16777216];               // final f [2048,512,2,2]
__device__ float g_hid[BATCH * GATEH];
__device__ float g_clean[BATCH * NEXP];
__device__ float g_rawstd[BATCH * NEXP];
__device__ float g_gates[BATCH * NEXP];
__device__ float g_prob[BATCH * NEXP];
__device__ float g_eh[(size_t)NEXP * BATCH * HID];
__device__ float g_eh2[(size_t)NEXP * BATCH * (HID / 2)];
__device__ float g_eo[(size_t)NEXP * BATCH * NCLS];
__device__ float g_imp[NEXP];
__device__ float g_load[NEXP];
__device__ int   g_rowlist[NEXP * BATCH];
__device__ int   g_cnt[NEXP];
__device__ int   g_rowslot[BATCH * 2];
__device__ float g_slotgate[NEXP * BATCH];

// ---------------- f32x2 helpers (packed dual-FMA, full-rate fp32) -------------
__device__ __forceinline__ u64 dupf(float v) {
  u64 r; asm("mov.b64 %0, {%1, %1};" : "=l"(r) : "f"(v)); return r;
}
__device__ __forceinline__ void fma2(u64& d, u64 a, u64 b) {
  asm("fma.rn.f32x2 %0, %1, %2, %0;" : "+l"(d) : "l"(a), "l"(b));
}
__device__ __forceinline__ float2 unp(u64 v) {
  float2 f; asm("mov.b64 {%0, %1}, %2;" : "=f"(f.x), "=f"(f.y) : "l"(v)); return f;
}

// =================== dense GEMM 128x64x16, f32x2 inner loop ===================
// C[m,n] = act(A[m,:] @ B[:,n] + bias[n]); optional row gather + per-z count.
#define DBM 128
#define DBN 64
#define DBK 16

__global__ __launch_bounds__(256) void gemm_f2(
    const float* __restrict__ A, const float* __restrict__ B,
    const float* __restrict__ bias, float* __restrict__ C,
    int M, int N, int K, int relu,
    long long sA, long long sB, long long sBias, long long sC,
    const int* __restrict__ rowlist, const int* __restrict__ cnt) {
  const int z = blockIdx.z;
  const int Mz = cnt ? cnt[z] : M;
  const int m0 = blockIdx.y * DBM;
  if (m0 >= Mz) return;
  const int n0 = blockIdx.x * DBN;

  const float* Ab = A + (long long)z * sA;
  const float* Bb = B + (long long)z * sB;
  const float* biasb = bias + (long long)z * sBias;
  float* Cb = C + (long long)z * sC;
  const int* rl = rowlist ? rowlist + z * BATCH : (const int*)0;

  __shared__ float As[DBK][DBM + 2];   // stride 130 floats (8B-multiple)
  __shared__ float Bs[DBK][DBN + 4];   // stride 68 floats (16B-multiple)

  u64 acc[4][4];
#pragma unroll
  for (int p = 0; p < 4; p++)
#pragma unroll
    for (int j = 0; j < 4; j++) acc[p][j] = 0ull;

  const int tid = threadIdx.x;
  const int tx = tid & 15, ty = tid >> 4;

  // A loader: 2 float4 per thread
  int rowA[2], kqA[2];
  size_t abase[2];
#pragma unroll
  for (int i = 0; i < 2; i++) {
    int v = tid + i * 256;
    rowA[i] = v >> 2;
    kqA[i] = v & 3;
    int gm = m0 + rowA[i];
    int ridx = rl ? ((gm < Mz) ? rl[gm] : 0) : gm;
    abase[i] = (size_t)ridx * K + kqA[i] * 4;
  }
  const int kb = tid >> 4, nb = (tid & 15) * 4;

  for (int k0 = 0; k0 < K; k0 += DBK) {
#pragma unroll
    for (int i = 0; i < 2; i++) {
      float4 a4 = *(const float4*)&Ab[abase[i] + k0];
      int kk = kqA[i] * 4;
      As[kk + 0][rowA[i]] = a4.x;
      As[kk + 1][rowA[i]] = a4.y;
      As[kk + 2][rowA[i]] = a4.z;
      As[kk + 3][rowA[i]] = a4.w;
    }
    {
      float4 b4;
      size_t bo = (size_t)(k0 + kb) * N + n0 + nb;
      if (n0 + nb + 3 < N) {
        b4 = *(const float4*)&Bb[bo];
      } else {
        b4.x = (n0 + nb + 0 < N) ? Bb[bo + 0] : 0.f;
        b4.y = (n0 + nb + 1 < N) ? Bb[bo + 1] : 0.f;
        b4.z = (n0 + nb + 2 < N) ? Bb[bo + 2] : 0.f;
        b4.w = (n0 + nb + 3 < N) ? Bb[bo + 3] : 0.f;
      }
      *(float4*)&Bs[kb][nb] = b4;
    }
    __syncthreads();
#pragma unroll
    for (int kk = 0; kk < DBK; kk++) {
      const u64* arow = (const u64*)&As[kk][0];
      u64 a0 = arow[ty * 4 + 0], a1 = arow[ty * 4 + 1];
      u64 a2 = arow[ty * 4 + 2], a3 = arow[ty * 4 + 3];
      float4 b4 = *(const float4*)&Bs[kk][tx * 4];
      u64 b0 = dupf(b4.x), b1 = dupf(b4.y), b2 = dupf(b4.z), b3 = dupf(b4.w);
      fma2(acc[0][0], a0, b0); fma2(acc[0][1], a0, b1);
      fma2(acc[0][2], a0, b2); fma2(acc[0][3], a0, b3);
      fma2(acc[1][0], a1, b0); fma2(acc[1][1], a1, b1);
      fma2(acc[1][2], a1, b2); fma2(acc[1][3], a1, b3);
      fma2(acc[2][0], a2, b0); fma2(acc[2][1], a2, b1);
      fma2(acc[2][2], a2, b2); fma2(acc[2][3], a2, b3);
      fma2(acc[3][0], a3, b0); fma2(acc[3][1], a3, b1);
      fma2(acc[3][2], a3, b2); fma2(acc[3][3], a3, b3);
    }
    __syncthreads();
  }

#pragma unroll
  for (int p = 0; p < 4; p++) {
    int mlo = m0 + ty * 8 + 2 * p;
#pragma unroll
    for (int j = 0; j < 4; j++) {
      int n = n0 + tx * 4 + j;
      if (n >= N) continue;
      float2 v = unp(acc[p][j]);
      float bsv = biasb[n];
      if (mlo < Mz) {
        float r = v.x + bsv;
        if (relu) r = fmaxf(r, 0.f);
        Cb[(size_t)mlo * N + n] = r;
      }
      if (mlo + 1 < Mz) {
        float r = v.y + bsv;
        if (relu) r = fmaxf(r, 0.f);
        Cb[(size_t)(mlo + 1) * N + n] = r;
      }
    }
  }
}

// ============ implicit-im2col conv 64x128x16 + bias/BN/ReLU, f32x2 ============
#define CBM 64
#define CBN 128
#define CBK 16

__global__ __launch_bounds__(256) void conv_f2(
    const float* __restrict__ in, const float* __restrict__ w,
    const float* __restrict__ cb, const float* __restrict__ gam,
    const float* __restrict__ bet, float* __restrict__ out,
    int Cin, int Cout, int H, int logW, int logHW) {
  const int HW = 1 << logHW;
  const int W = 1 << logW;
  const int Ktot = Cin * 9;
  const int n0 = blockIdx.x * CBN;
  const int m0 = blockIdx.y * CBM;

  __shared__ float As[CBK][CBM + 2];   // stride 66 floats (8B-mult)
  __shared__ float Bs[CBK][CBN + 4];

  u64 acc[4][4];
#pragma unroll
  for (int p = 0; p < 4; p++)
#pragma unroll
    for (int j = 0; j < 4; j++) acc[p][j] = 0ull;

  const int tid = threadIdx.x;
  const int tx = tid & 31, ty = tid >> 5;
  const int kB = tid >> 4, nb8 = (tid & 15) * 8;

  for (int k0 = 0; k0 < Ktot; k0 += CBK) {
    // A (weights): 4 scalar guarded loads per thread
#pragma unroll
    for (int i = 0; i < 4; i++) {
      int l = tid + i * 256;
      int k = l & 15, m = l >> 4;
      int gk = k0 + k;
      As[k][m] = (gk < Ktot) ? w[(m0 + m) * Ktot + gk] : 0.f;
    }
    // B (im2col gather): one k per thread, 8 consecutive n
    {
      int gk = k0 + kB;
      int ci = 0, ky = 0, kx = 0;
      bool kvalid = gk < Ktot;
      if (kvalid) {
        ci = gk / 9;
        int r = gk - ci * 9;
        ky = r / 3;
        kx = r - ky * 3;
      }
      const float* inp = in + (size_t)ci * HW;  // offset within image
#pragma unroll
      for (int jj = 0; jj < 8; jj++) {
        int gn = n0 + nb8 + jj;
        float v = 0.f;
        if (kvalid) {
          int b = gn >> logHW;
          int pos = gn & (HW - 1);
          int y = pos >> logW, x = pos & (W - 1);
          int iy = y + ky - 1, ix = x + kx - 1;
          if ((unsigned)iy < (unsigned)H && (unsigned)ix < (unsigned)H)
            v = inp[((size_t)b * Cin << logHW) + (iy << logW) + ix];
        }
        Bs[kB][nb8 + jj] = v;
      }
    }
    __syncthreads();
#pragma unroll
    for (int kk = 0; kk < CBK; kk++) {
      const u64* arow = (const u64*)&As[kk][0];
      u64 a0 = arow[ty * 4 + 0], a1 = arow[ty * 4 + 1];
      u64 a2 = arow[ty * 4 + 2], a3 = arow[ty * 4 + 3];
      float4 b4 = *(const float4*)&Bs[kk][tx * 4];
      u64 b0 = dupf(b4.x), b1 = dupf(b4.y), b2 = dupf(b4.z), b3 = dupf(b4.w);
      fma2(acc[0][0], a0, b0); fma2(acc[0][1], a0, b1);
      fma2(acc[0][2], a0, b2); fma2(acc[0][3], a0, b3);
      fma2(acc[1][0], a1, b0); fma2(acc[1][1], a1, b1);
      fma2(acc[1][2], a1, b2); fma2(acc[1][3], a1, b3);
      fma2(acc[2][0], a2, b0); fma2(acc[2][1], a2, b1);
      fma2(acc[2][2], a2, b2); fma2(acc[2][3], a2, b3);
      fma2(acc[3][0], a3, b0); fma2(acc[3][1], a3, b1);
      fma2(acc[3][2], a3, b2); fma2(acc[3][3], a3, b3);
    }
    __syncthreads();
  }

  const float rs = rsqrtf(1.00001f);
#pragma unroll
  for (int p = 0; p < 4; p++) {
    int mlo = m0 + ty * 8 + 2 * p;
    float sc0 = gam[mlo] * rs, cb0 = cb[mlo], be0 = bet[mlo];
    float sc1 = gam[mlo + 1] * rs, cb1v = cb[mlo + 1], be1v = bet[mlo + 1];
#pragma unroll
    for (int j = 0; j < 4; j++) {
      int gn = n0 + tx * 4 + j;
      int b = gn >> logHW;
      int pos = gn & (HW - 1);
      float2 v = unp(acc[p][j]);
      float r0 = fmaxf((v.x + cb0) * sc0 + be0, 0.f);
      float r1 = fmaxf((v.y + cb1v) * sc1 + be1v, 0.f);
      out[((size_t)(b * Cout + mlo) << logHW) + pos] = r0;
      out[((size_t)(b * Cout + mlo + 1) << logHW) + pos] = r1;
    }
  }
}

// ---------------- 2x2 max pool (stride 2) ----------------
__global__ void pool_kernel(const float* __restrict__ in, float* __restrict__ out,
                            int C, int H) {
  int Hp = H >> 1;
  int total = BATCH * C * Hp * Hp;
  int idx = blockIdx.x * blockDim.x + threadIdx.x;
  if (idx >= total) return;
  int px = idx % Hp;
  int t = idx / Hp;
  int py = t % Hp; t /= Hp;
  int c = t % C;
  int b = t / C;
  const float* p = in + ((size_t)(b * C + c) * H + py * 2) * H + px * 2;
  out[idx] = fmaxf(fmaxf(p[0], p[1]), fmaxf(p[H], p[H + 1]));
}

// ---------------- noisy top-k gating (per row) ----------------
__global__ void gating_kernel(const float* __restrict__ clean,
                              const float* __restrict__ rawstd,
                              const float* __restrict__ noise,
                              float* __restrict__ gates, float* __restrict__ prob) {
  int b = blockIdx.x * blockDim.x + threadIdx.x;
  if (b >= BATCH) return;
  float c[NEXP], sd[NEXP], nz[NEXP];
#pragma unroll
  for (int e = 0; e < NEXP; e++) {
    c[e] = clean[b * NEXP + e];
    float rsv = rawstd[b * NEXP + e];
    float sp = (rsv > 20.f) ? rsv : log1pf(expf(rsv));
    sd[e] = sp + 0.01f;
    nz[e] = c[e] + noise[b * NEXP + e] * sd[e];
  }
  int i0 = 0; float v0 = nz[0];
#pragma unroll
  for (int e = 1; e < NEXP; e++) if (nz[e] > v0) { v0 = nz[e]; i0 = e; }
  int i1 = -1; float v1 = -1e30f;
#pragma unroll
  for (int e = 0; e < NEXP; e++) if (e != i0 && nz[e] > v1) { v1 = nz[e]; i1 = e; }
  float v2 = -1e30f;
#pragma unroll
  for (int e = 0; e < NEXP; e++) if (e != i0 && e != i1 && nz[e] > v2) v2 = nz[e];

  float e1 = expf(v1 - v0);
  float inv = 1.f / (1.f + e1);
  const float kInvSqrt2 = 0.70710678118654752440f;
#pragma unroll
  for (int e = 0; e < NEXP; e++) {
    float g = (e == i0) ? inv : ((e == i1) ? e1 * inv : 0.f);
    gates[b * NEXP + e] = g;
    float th = (nz[e] > v2) ? v2 : v1;
    float z = (c[e] - th) / sd[e];
    prob[b * NEXP + e] = 0.5f * (1.f + erff(z * kInvSqrt2));
  }
}

// -------- deterministic dispatch build (1 block, warp per expert) --------
__global__ void build_dispatch(const float* __restrict__ gates,
                               int* __restrict__ rowlist, int* __restrict__ cnt,
                               int* __restrict__ rowslot,
                               float* __restrict__ slotgate) {
  int w = threadIdx.x >> 5;
  int lane = threadIdx.x & 31;
  int c = 0;
  for (int base = 0; base < BATCH; base += 32) {
    int b = base + lane;
    float g = gates[b * NEXP + w];
    unsigned mask = __ballot_sync(0xffffffffu, g > 0.f);
    if (g > 0.f) {
      int pos = c + __popc(mask & ((1u << lane) - 1u));
      int slot = w * BATCH + pos;
      rowlist[slot] = b;
      slotgate[slot] = g;
      int m8 = 0;
#pragma unroll
      for (int e = 0; e < NEXP; e++) m8 |= (gates[b * NEXP + e] > 0.f) ? (1 << e) : 0;
      int j = __popc(m8 & ((1 << w) - 1));
      rowslot[b * 2 + j] = slot;
    }
    c += __popc(mask);
  }
  if (lane == 0) cnt[w] = c;
}

// ---------------- deterministic per-expert reductions ----------------
__global__ void moe_reduce_kernel(const float* __restrict__ gates,
                                  const float* __restrict__ prob,
                                  float* __restrict__ imp, float* __restrict__ loadv) {
  int e = blockIdx.x;
  int t = threadIdx.x;
  __shared__ float s1[256], s2[256];
  float a = 0.f, b = 0.f;
  for (int i = t; i < BATCH; i += 256) {
    a += gates[i * NEXP + e];
    b += prob[i * NEXP + e];
  }
  s1[t] = a; s2[t] = b;
  __syncthreads();
  for (int s = 128; s > 0; s >>= 1) {
    if (t < s) { s1[t] += s1[t + s]; s2[t] += s2[t + s]; }
    __syncthreads();
  }
  if (t == 0) { imp[e] = s1[0]; loadv[e] = s2[0]; }
}

__global__ void loss_kernel(const float* __restrict__ imp,
                            const float* __restrict__ loadv,
                            float* __restrict__ out) {
  float m1 = 0.f, m2 = 0.f;
  for (int e = 0; e < NEXP; e++) { m1 += imp[e]; m2 += loadv[e]; }
  m1 *= 0.125f; m2 *= 0.125f;
  float v1 = 0.f, v2 = 0.f;
  for (int e = 0; e < NEXP; e++) {
    float d1 = imp[e] - m1; v1 += d1 * d1;
    float d2 = loadv[e] - m2; v2 += d2 * d2;
  }
  v1 /= 7.f; v2 /= 7.f;
  out[0] = v1 / (m1 * m1 + 1e-10f) + v2 / (m2 * m2 + 1e-10f);
}

// ------------- slot-based combine: y[b,c] = g0*eo[s0,c]+g1*eo[s1,c] ----------
__global__ void combine2_kernel(const int* __restrict__ rowslot,
                                const float* __restrict__ slotgate,
                                const float* __restrict__ eo,
                                float* __restrict__ y) {
  int idx = blockIdx.x * blockDim.x + threadIdx.x;
  if (idx >= BATCH * NCLS) return;
  int b = idx / NCLS;
  int c = idx - b * NCLS;
  int s0 = rowslot[b * 2 + 0], s1 = rowslot[b * 2 + 1];
  y[idx] = slotgate[s0] * eo[(size_t)s0 * NCLS + c] +
           slotgate[s1] * eo[(size_t)s1 * NCLS + c];
}

// ================================ launch ======================================
extern "C" void kernel_launch(void* const* d_in, const int* in_sizes, int n_in,
                              void* d_out, int out_size) {
  const float* x    = (const float*)d_in[0];
  const float* noise= (const float*)d_in[1];
  const float* cw1 = (const float*)d_in[2],  *cb1 = (const float*)d_in[3];
  const float* g1  = (const float*)d_in[4],  *be1 = (const float*)d_in[5];
  const float* cw2 = (const float*)d_in[6],  *cb2 = (const float*)d_in[7];
  const float* g2  = (const float*)d_in[8],  *be2 = (const float*)d_in[9];
  const float* cw3 = (const float*)d_in[10], *cb3 = (const float*)d_in[11];
  const float* g3  = (const float*)d_in[12], *be3 = (const float*)d_in[13];
  const float* cw4 = (const float*)d_in[14], *cb4 = (const float*)d_in[15];
  const float* g4  = (const float*)d_in[16], *be4 = (const float*)d_in[17];
  const float* wg1 = (const float*)d_in[18], *wg1b= (const float*)d_in[19];
  const float* wg2 = (const float*)d_in[20], *wg2b= (const float*)d_in[21];
  const float* wn1 = (const float*)d_in[22], *wn1b= (const float*)d_in[23];
  const float* wn2 = (const float*)d_in[24], *wn2b= (const float*)d_in[25];
  const float* eW1 = (const float*)d_in[26], *eb1 = (const float*)d_in[27];
  const float* eW2 = (const float*)d_in[28], *eb2 = (const float*)d_in[29];
  const float* eW3 = (const float*)d_in[30], *eb3 = (const float*)d_in[31];

  float *convout, *poolA, *poolB, *hid, *clean, *rawstd, *gates, *prob;
  float *eh, *eh2, *eo, *imp, *loadv, *slotgate;
  int *rowlist, *cnt, *rowslot;
  cudaGetSymbolAddress((void**)&convout, g_convout);
  cudaGetSymbolAddress((void**)&poolA, g_poolA);
  cudaGetSymbolAddress((void**)&poolB, g_poolB);
  cudaGetSymbolAddress((void**)&hid, g_hid);
  cudaGetSymbolAddress((void**)&clean, g_clean);
  cudaGetSymbolAddress((void**)&rawstd, g_rawstd);
  cudaGetSymbolAddress((void**)&gates, g_gates);
  cudaGetSymbolAddress((void**)&prob, g_prob);
  cudaGetSymbolAddress((void**)&eh, g_eh);
  cudaGetSymbolAddress((void**)&eh2, g_eh2);
  cudaGetSymbolAddress((void**)&eo, g_eo);
  cudaGetSymbolAddress((void**)&imp, g_imp);
  cudaGetSymbolAddress((void**)&loadv, g_load);
  cudaGetSymbolAddress((void**)&rowlist, g_rowlist);
  cudaGetSymbolAddress((void**)&cnt, g_cnt);
  cudaGetSymbolAddress((void**)&rowslot, g_rowslot);
  cudaGetSymbolAddress((void**)&slotgate, g_slotgate);

  float* out = (float*)d_out;

  // ---- conv stack ----
  conv_f2<<<dim3(BATCH * 1024 / CBN, 1), 256>>>(x, cw1, cb1, g1, be1, convout, 3, 64, 32, 5, 10);
  pool_kernel<<<(BATCH * 64 * 256 + 255) / 256, 256>>>(convout, poolA, 64, 32);

  conv_f2<<<dim3(BATCH * 256 / CBN, 2), 256>>>(poolA, cw2, cb2, g2, be2, convout, 64, 128, 16, 4, 8);
  pool_kernel<<<(BATCH * 128 * 64 + 255) / 256, 256>>>(convout, poolB, 128, 16);

  conv_f2<<<dim3(BATCH * 64 / CBN, 4), 256>>>(poolB, cw3, cb3, g3, be3, convout, 128, 256, 8, 3, 6);
  pool_kernel<<<(BATCH * 256 * 16 + 255) / 256, 256>>>(convout, poolA, 256, 8);

  conv_f2<<<dim3(BATCH * 16 / CBN, 8), 256>>>(poolA, cw4, cb4, g4, be4, convout, 256, 512, 4, 2, 4);
  pool_kernel<<<(BATCH * 512 * 4 + 255) / 256, 256>>>(convout, poolB, 512, 4);

  const float* f = poolB;  // [2048, 2048]

  // ---- gating nets ----
  gemm_f2<<<dim3(GATEH / DBN, BATCH / DBM, 1), 256>>>(
      f, wg1, wg1b, hid, BATCH, GATEH, FEAT, 1, 0, 0, 0, 0, 0, 0);
  gemm_f2<<<dim3(1, BATCH / DBM, 1), 256>>>(
      hid, wg2, wg2b, clean, BATCH, NEXP, GATEH, 0, 0, 0, 0, 0, 0, 0);
  gemm_f2<<<dim3(GATEH / DBN, BATCH / DBM, 1), 256>>>(
      f, wn1, wn1b, hid, BATCH, GATEH, FEAT, 1, 0, 0, 0, 0, 0, 0);
  gemm_f2<<<dim3(1, BATCH / DBM, 1), 256>>>(
      hid, wn2, wn2b, rawstd, BATCH, NEXP, GATEH, 0, 0, 0, 0, 0, 0, 0);

  gating_kernel<<<BATCH / 256, 256>>>(clean, rawstd, noise, gates, prob);
  build_dispatch<<<1, 256>>>(gates, rowlist, cnt, rowslot, slotgate);
  moe_reduce_kernel<<<NEXP, 256>>>(gates, prob, imp, loadv);

  // ---- sparse experts (capacity grid, early-exit on cnt) ----
  gemm_f2<<<dim3(HID / DBN, BATCH / DBM, NEXP), 256>>>(
      f, eW1, eb1, eh, BATCH, HID, FEAT, 1,
      0, (long long)FEAT * HID, HID, (long long)BATCH * HID, rowlist, cnt);
  gemm_f2<<<dim3((HID / 2) / DBN, BATCH / DBM, NEXP), 256>>>(
      eh, eW2, eb2, eh2, BATCH, HID / 2, HID, 1,
      (long long)BATCH * HID, (long long)HID * (HID / 2), HID / 2,
      (long long)BATCH * (HID / 2), 0, cnt);
  gemm_f2<<<dim3((NCLS + DBN - 1) / DBN, BATCH / DBM, NEXP), 256>>>(
      eh2, eW3, eb3, eo, BATCH, NCLS, HID / 2, 0,
      (long long)BATCH * (HID / 2), (long long)(HID / 2) * NCLS, NCLS,
      (long long)BATCH * NCLS, 0, cnt);

  // ---- outputs ----
  combine2_kernel<<<(BATCH * NCLS + 255) / 256, 256>>>(rowslot, slotgate, eo, out);
  if (out_size >= BATCH * NCLS + 1)
    loss_kernel<<<1, 1>>>(imp, loadv, out + BATCH * NCLS);
}